// round 10
// baseline (speedup 1.0000x reference)
#include <cuda_runtime.h>
#include <cstdint>

// x: (131072, 28, 28) fp32. rows = 4 int32, cols = 4 int32.
// out[i,h,w] = mute(x) if (h in rows) || (w in cols) else x
// mute idempotent -> single mask test. 256-bit (v8) global loads/stores (sm_100+).
// Mask = f(float8_index % 98), 98-entry 8-bit smem LUT (groups may cross rows,
// never images since 8 | 784). Incremental phase: step 256 mod 98 == 60.

static constexpr int HW8 = 98;                      // float8 groups per image
static constexpr long long NELEM = 131072LL * 784;  // 102,760,448
static constexpr int N8 = (int)(NELEM / 8);         // 12,845,056 = 25088 * 512
static constexpr int UNROLL = 2;
static constexpr int THREADS = 256;
static constexpr int STEP = THREADS % HW8;          // 60

__device__ __forceinline__ unsigned mute1u(unsigned b) {
    unsigned ef = b & 0x7F800000u;                   // exponent field in place
    unsigned b2 = (b & 0x807FFFFFu) | 0x3F000000u;   // exponent -> 126
    // biased exp in [128,254]  <=>  ef in [0x40000000, 0x7F800000)
    return (ef - 0x40000000u < 0x3F800000u) ? b2 : b;
}

struct U8 { unsigned r[8]; };

__device__ __forceinline__ U8 ldg256(const unsigned* p) {
    U8 v;
    asm volatile("ld.global.v8.b32 {%0,%1,%2,%3,%4,%5,%6,%7}, [%8];"
        : "=r"(v.r[0]), "=r"(v.r[1]), "=r"(v.r[2]), "=r"(v.r[3]),
          "=r"(v.r[4]), "=r"(v.r[5]), "=r"(v.r[6]), "=r"(v.r[7])
        : "l"(p));
    return v;
}

__device__ __forceinline__ void stg256(unsigned* p, const U8& v) {
    asm volatile("st.global.v8.b32 [%0], {%1,%2,%3,%4,%5,%6,%7,%8};"
        :: "l"(p),
           "r"(v.r[0]), "r"(v.r[1]), "r"(v.r[2]), "r"(v.r[3]),
           "r"(v.r[4]), "r"(v.r[5]), "r"(v.r[6]), "r"(v.r[7])
        : "memory");
}

__global__ void __launch_bounds__(THREADS) mute_kernel(
    const unsigned* __restrict__ x,
    const int* __restrict__ rows,
    const int* __restrict__ cols,
    unsigned* __restrict__ out)
{
    __shared__ unsigned char lut[HW8];

    int tid = threadIdx.x;
    if (tid < HW8) {
        int r0 = rows[0], r1 = rows[1], r2 = rows[2], r3 = rows[3];
        int c0 = cols[0], c1 = cols[1], c2 = cols[2], c3 = cols[3];
        unsigned m = 0;
        #pragma unroll
        for (int k = 0; k < 8; k++) {
            int p = tid * 8 + k;            // element offset within 28x28 image
            int h = p / 28;
            int w = p - h * 28;
            bool rm = (h == r0) | (h == r1) | (h == r2) | (h == r3);
            bool cm = (w == c0) | (w == c1) | (w == c2) | (w == c3);
            if (rm | cm) m |= (1u << k);
        }
        lut[tid] = (unsigned char)m;
    }
    __syncthreads();

    int base = blockIdx.x * (THREADS * UNROLL) + tid;   // float8 units

    // Front-batch 2 LDG.256s (64B in flight per thread)
    U8 v[UNROLL];
    #pragma unroll
    for (int k = 0; k < UNROLL; k++) {
        v[k] = ldg256(x + (size_t)(base + k * THREADS) * 8);
    }

    int ph = base % HW8;

    #pragma unroll
    for (int k = 0; k < UNROLL; k++) {
        unsigned m = lut[ph];
        #pragma unroll
        for (int j = 0; j < 8; j++) {
            if (m & (1u << j)) v[k].r[j] = mute1u(v[k].r[j]);
        }
        stg256(out + (size_t)(base + k * THREADS) * 8, v[k]);
        ph += STEP;
        if (ph >= HW8) ph -= HW8;
    }
}

extern "C" void kernel_launch(void* const* d_in, const int* in_sizes, int n_in,
                              void* d_out, int out_size) {
    const unsigned* x = (const unsigned*)d_in[0];
    const int* rows   = (const int*)d_in[1];
    const int* cols   = (const int*)d_in[2];
    unsigned* out     = (unsigned*)d_out;

    const int blocks = N8 / (THREADS * UNROLL);  // 25,088 exact
    mute_kernel<<<blocks, THREADS>>>(x, rows, cols, out);
}

// round 11
// speedup vs baseline: 1.0102x; 1.0102x over previous
#include <cuda_runtime.h>
#include <cstdint>

// FINAL (R5 config — best measured wall time 122.27us, kernel 115.8us, rel_err 0.0).
//
// x: (131072, 28, 28) fp32. rows = 4 int32, cols = 4 int32.
// out[i,h,w] = mute(x) if (h in rows) || (w in cols) else x
//   mute(x): frexp e>1  =>  replace exponent field with 126 (|x|>=2 -> [0.5,1)),
//   exact bit manipulation, idempotent => row-then-col order collapses to one mask.
// Mask = f(float4_index % 196) via per-block smem LUT; phase tracked
// incrementally (step 256 mod 196 == 60) to avoid per-iter IMAD-mod chains.
// UNROLL=4 front-batched LDG.128s (MLP=4), 256 threads, 27 regs, occ 84%.
// Measured at the mixed R/W HBM ceiling (~6.63 TB/s, DRAM pipe 83.7%): deeper
// unroll, 512-thread blocks, v8 256-bit accesses, streaming hints, and a
// persistent grid were all benchmarked and are neutral-or-worse.

static constexpr int HW4 = 196;                     // float4 positions per image
static constexpr long long NELEM = 131072LL * 784;  // 102,760,448
static constexpr int N4 = (int)(NELEM / 4);         // 25,690,112 = 25088 * 1024
static constexpr int UNROLL = 4;
static constexpr int THREADS = 256;
static constexpr int STEP = 256 % HW4;              // 60

__device__ __forceinline__ float mute1(float x) {
    unsigned b  = __float_as_uint(x);
    unsigned ef = b & 0x7F800000u;                   // exponent field in place
    unsigned b2 = (b & 0x807FFFFFu) | 0x3F000000u;   // exponent -> 126
    // biased exp in [128,254]  <=>  ef in [0x40000000, 0x7F800000)
    // (excludes inf/nan at 255; subnormals/zero have ef < threshold)
    return __uint_as_float((ef - 0x40000000u < 0x3F800000u) ? b2 : b);
}

__global__ void __launch_bounds__(THREADS) mute_kernel(
    const float4* __restrict__ x,
    const int* __restrict__ rows,
    const int* __restrict__ cols,
    float4* __restrict__ out)
{
    __shared__ unsigned char lut[HW4];

    int tid = threadIdx.x;
    if (tid < HW4) {
        int p = tid * 4;          // element offset within 28x28 image
        int h = p / 28;
        int w = p - h * 28;       // float4 never crosses a row (4 | 28)
        int r0 = rows[0], r1 = rows[1], r2 = rows[2], r3 = rows[3];
        int c0 = cols[0], c1 = cols[1], c2 = cols[2], c3 = cols[3];
        bool rm = (h == r0) | (h == r1) | (h == r2) | (h == r3);
        unsigned m = 0;
        #pragma unroll
        for (int k = 0; k < 4; k++) {
            bool cm = (w + k == c0) | (w + k == c1) | (w + k == c2) | (w + k == c3);
            if (rm | cm) m |= (1u << k);
        }
        lut[tid] = (unsigned char)m;
    }
    __syncthreads();

    int base = blockIdx.x * (THREADS * UNROLL) + tid;

    // Front-batch 4 LDG.128s (MLP=4), default caching
    float4 v[UNROLL];
    #pragma unroll
    for (int k = 0; k < UNROLL; k++) {
        v[k] = x[base + k * THREADS];
    }

    // Incremental phase: (base + k*256) % 196
    int ph = base % HW4;

    #pragma unroll
    for (int k = 0; k < UNROLL; k++) {
        unsigned m = lut[ph];
        v[k].x = (m & 1u) ? mute1(v[k].x) : v[k].x;
        v[k].y = (m & 2u) ? mute1(v[k].y) : v[k].y;
        v[k].z = (m & 4u) ? mute1(v[k].z) : v[k].z;
        v[k].w = (m & 8u) ? mute1(v[k].w) : v[k].w;
        out[base + k * THREADS] = v[k];
        ph += STEP;
        if (ph >= HW4) ph -= HW4;
    }
}

extern "C" void kernel_launch(void* const* d_in, const int* in_sizes, int n_in,
                              void* d_out, int out_size) {
    const float4* x = (const float4*)d_in[0];
    const int* rows = (const int*)d_in[1];
    const int* cols = (const int*)d_in[2];
    float4* out     = (float4*)d_out;

    const int blocks = N4 / (THREADS * UNROLL);  // 25,088 exact
    mute_kernel<<<blocks, THREADS>>>(x, rows, cols, out);
}